// round 1
// baseline (speedup 1.0000x reference)
#include <cuda_runtime.h>

// Problem constants
#define B_  4
#define L_  2048
#define D_  512
#define H_  8
#define DK_ 64
#define M_  (B_ * L_)   // 8192 rows for all projection GEMMs

// Scratch: Q/K/V projections in [B, L, H, DK] layout, and the attention
// output in the reference's "buggy" flattening order [H, Lq, B, Dv].
__device__ float g_q[B_ * L_ * H_ * DK_];
__device__ float g_k[B_ * L_ * H_ * DK_];
__device__ float g_v[B_ * L_ * H_ * DK_];
__device__ float g_xt[B_ * L_ * H_ * DK_];

// ---------------------------------------------------------------------------
// GEMM + bias: C[M,N] = A[M,K] @ W[K,N] + bias[N]
// 64x64 tile, BK=32, 256 threads, 4x4 microtile per thread.
// As stored transposed [k][m] (pitch 68) so both operands read as LDS.128.
// ---------------------------------------------------------------------------
__global__ __launch_bounds__(256)
void gemm_bias_kernel(const float* __restrict__ A, const float* __restrict__ W,
                      const float* __restrict__ bias, float* __restrict__ C,
                      int M, int N, int K)
{
    __shared__ float As[32][68];
    __shared__ float Ws[32][68];

    const int tid = threadIdx.x;
    const int tx = tid & 15;        // 0..15 -> 4 output cols each
    const int ty = tid >> 4;        // 0..15 -> 4 output rows each
    const int m0 = blockIdx.x << 6;
    const int n0 = blockIdx.y << 6;

    float acc[4][4];
#pragma unroll
    for (int i = 0; i < 4; i++)
#pragma unroll
        for (int j = 0; j < 4; j++) acc[i][j] = 0.f;

    for (int kb = 0; kb < K; kb += 32) {
        // A tile: 64 rows x 32 k, transposed store
#pragma unroll
        for (int i = 0; i < 2; i++) {
            int f   = tid + (i << 8);
            int row = f >> 3;             // 0..63
            int kq  = (f & 7) << 2;       // 0,4,...,28
            float4 a4 = *reinterpret_cast<const float4*>(
                A + (size_t)(m0 + row) * K + kb + kq);
            As[kq + 0][row] = a4.x;
            As[kq + 1][row] = a4.y;
            As[kq + 2][row] = a4.z;
            As[kq + 3][row] = a4.w;
        }
        // W tile: 32 k x 64 cols, natural store
#pragma unroll
        for (int i = 0; i < 2; i++) {
            int f  = tid + (i << 8);
            int kk = f >> 4;              // 0..31
            int nq = (f & 15) << 2;       // 0,4,...,60
            *reinterpret_cast<float4*>(&Ws[kk][nq]) =
                *reinterpret_cast<const float4*>(
                    W + (size_t)(kb + kk) * N + n0 + nq);
        }
        __syncthreads();

#pragma unroll
        for (int kk = 0; kk < 32; kk++) {
            float4 a4 = *reinterpret_cast<const float4*>(&As[kk][ty << 2]);
            float4 w4 = *reinterpret_cast<const float4*>(&Ws[kk][tx << 2]);
            float a[4] = {a4.x, a4.y, a4.z, a4.w};
            float w[4] = {w4.x, w4.y, w4.z, w4.w};
#pragma unroll
            for (int i = 0; i < 4; i++)
#pragma unroll
                for (int j = 0; j < 4; j++)
                    acc[i][j] = fmaf(a[i], w[j], acc[i][j]);
        }
        __syncthreads();
    }

    float4 b4 = *reinterpret_cast<const float4*>(bias + n0 + (tx << 2));
#pragma unroll
    for (int i = 0; i < 4; i++) {
        float4 o;
        o.x = acc[i][0] + b4.x;
        o.y = acc[i][1] + b4.y;
        o.z = acc[i][2] + b4.z;
        o.w = acc[i][3] + b4.w;
        *reinterpret_cast<float4*>(
            C + (size_t)(m0 + (ty << 2) + i) * N + n0 + (tx << 2)) = o;
    }
}

// ---------------------------------------------------------------------------
// Fused flash attention (fp32, online softmax).
// Block = one (b, h, 64-query tile). 256 threads, 4x4 microtiles.
// smem: Qs/Ks transposed [d][row] pitch 68; Vs [k][d] pitch 64; Ps [row][k] pitch 64.
// Epilogue writes g_xt in the reference's [H, Lq, B, Dv] flat order.
// ---------------------------------------------------------------------------
#define FLASH_SMEM ((64 * 68 * 2 + 64 * 64 * 2) * 4)

__global__ __launch_bounds__(256)
void flash_kernel(const float* __restrict__ mask)
{
    extern __shared__ float sm[];
    float* Qs = sm;                 // [64][68]  Qs[d*68 + row]
    float* Ks = Qs + 64 * 68;       // [64][68]  Ks[d*68 + col]
    float* Vs = Ks + 64 * 68;       // [64][64]  Vs[k*64 + d]
    float* Ps = Vs + 64 * 64;       // [64][64]  Ps[row*64 + k]

    const int tid = threadIdx.x;
    const int tx = tid & 15;
    const int ty = tid >> 4;
    const int q0 = blockIdx.x << 6;
    const int h  = blockIdx.y;
    const int b  = blockIdx.z;
    const float scale = 0.125f;     // 1/sqrt(64)

    // Load Q tile (64 rows x 64 dims), transposed into Qs[d][row]
#pragma unroll
    for (int i = 0; i < 4; i++) {
        int f   = tid + (i << 8);
        int row = f >> 4;            // 0..63
        int dq  = (f & 15) << 2;     // 0,4,...,60
        float4 v = *reinterpret_cast<const float4*>(
            g_q + (((size_t)b * L_ + q0 + row) * H_ + h) * DK_ + dq);
        Qs[(dq + 0) * 68 + row] = v.x;
        Qs[(dq + 1) * 68 + row] = v.y;
        Qs[(dq + 2) * 68 + row] = v.z;
        Qs[(dq + 3) * 68 + row] = v.w;
    }

    float m_i[4], l_i[4], o[4][4];
#pragma unroll
    for (int i = 0; i < 4; i++) {
        m_i[i] = -1e30f;
        l_i[i] = 0.f;
#pragma unroll
        for (int j = 0; j < 4; j++) o[i][j] = 0.f;
    }

    for (int k0 = 0; k0 < L_; k0 += 64) {
        __syncthreads();  // previous PV done before overwriting K/V (also fences Q load on iter 0)

        // Load K (transposed) and V (natural) tiles
#pragma unroll
        for (int i = 0; i < 4; i++) {
            int f   = tid + (i << 8);
            int row = f >> 4;
            int dq  = (f & 15) << 2;
            size_t base = (((size_t)b * L_ + k0 + row) * H_ + h) * DK_ + dq;
            float4 kv = *reinterpret_cast<const float4*>(g_k + base);
            Ks[(dq + 0) * 68 + row] = kv.x;
            Ks[(dq + 1) * 68 + row] = kv.y;
            Ks[(dq + 2) * 68 + row] = kv.z;
            Ks[(dq + 3) * 68 + row] = kv.w;
            float4 vv = *reinterpret_cast<const float4*>(g_v + base);
            *reinterpret_cast<float4*>(&Vs[row * 64 + dq]) = vv;
        }
        __syncthreads();

        // S = Q K^T (4x4 per thread)
        float s[4][4];
#pragma unroll
        for (int i = 0; i < 4; i++)
#pragma unroll
            for (int j = 0; j < 4; j++) s[i][j] = 0.f;

#pragma unroll 8
        for (int d = 0; d < 64; d++) {
            float4 a4 = *reinterpret_cast<const float4*>(&Qs[d * 68 + (ty << 2)]);
            float4 k4 = *reinterpret_cast<const float4*>(&Ks[d * 68 + (tx << 2)]);
            float a[4] = {a4.x, a4.y, a4.z, a4.w};
            float k[4] = {k4.x, k4.y, k4.z, k4.w};
#pragma unroll
            for (int i = 0; i < 4; i++)
#pragma unroll
                for (int j = 0; j < 4; j++)
                    s[i][j] = fmaf(a[i], k[j], s[i][j]);
        }

        // scale + additive mask
#pragma unroll
        for (int i = 0; i < 4; i++) {
            float4 mv = *reinterpret_cast<const float4*>(
                mask + (size_t)(q0 + (ty << 2) + i) * L_ + k0 + (tx << 2));
            s[i][0] = fmaf(s[i][0], scale, mv.x);
            s[i][1] = fmaf(s[i][1], scale, mv.y);
            s[i][2] = fmaf(s[i][2], scale, mv.z);
            s[i][3] = fmaf(s[i][3], scale, mv.w);
        }

        // online softmax update (row groups of 16 lanes along tx)
#pragma unroll
        for (int i = 0; i < 4; i++) {
            float mt = fmaxf(fmaxf(s[i][0], s[i][1]), fmaxf(s[i][2], s[i][3]));
#pragma unroll
            for (int off = 8; off >= 1; off >>= 1)
                mt = fmaxf(mt, __shfl_xor_sync(0xffffffffu, mt, off, 16));
            float mn = fmaxf(m_i[i], mt);
            float alpha = __expf(m_i[i] - mn);
            m_i[i] = mn;
            float rs = 0.f;
#pragma unroll
            for (int j = 0; j < 4; j++) {
                s[i][j] = __expf(s[i][j] - mn);
                rs += s[i][j];
            }
#pragma unroll
            for (int off = 8; off >= 1; off >>= 1)
                rs += __shfl_xor_sync(0xffffffffu, rs, off, 16);
            l_i[i] = l_i[i] * alpha + rs;
#pragma unroll
            for (int j = 0; j < 4; j++) o[i][j] *= alpha;

            float4 p4 = {s[i][0], s[i][1], s[i][2], s[i][3]};
            *reinterpret_cast<float4*>(&Ps[((ty << 2) + i) * 64 + (tx << 2)]) = p4;
        }
        __syncthreads();

        // O += P V
#pragma unroll 8
        for (int kk = 0; kk < 64; kk++) {
            float4 v4 = *reinterpret_cast<const float4*>(&Vs[kk * 64 + (tx << 2)]);
#pragma unroll
            for (int i = 0; i < 4; i++) {
                float p = Ps[((ty << 2) + i) * 64 + kk];
                o[i][0] = fmaf(p, v4.x, o[i][0]);
                o[i][1] = fmaf(p, v4.y, o[i][1]);
                o[i][2] = fmaf(p, v4.z, o[i][2]);
                o[i][3] = fmaf(p, v4.w, o[i][3]);
            }
        }
    }

    // Epilogue: write in reference's flattening order [H, Lq, B, Dv]
#pragma unroll
    for (int i = 0; i < 4; i++) {
        float inv = 1.0f / l_i[i];
        int row = q0 + (ty << 2) + i;
        float4 out = {o[i][0] * inv, o[i][1] * inv, o[i][2] * inv, o[i][3] * inv};
        *reinterpret_cast<float4*>(
            g_xt + (((size_t)h * L_ + row) * B_ + b) * DK_ + (tx << 2)) = out;
    }
}

// ---------------------------------------------------------------------------
extern "C" void kernel_launch(void* const* d_in, const int* in_sizes, int n_in,
                              void* d_out, int out_size)
{
    const float* query = (const float*)d_in[0];
    const float* key   = (const float*)d_in[1];
    const float* value = (const float*)d_in[2];
    const float* mask  = (const float*)d_in[3];
    const float* Wq    = (const float*)d_in[4];
    const float* bq    = (const float*)d_in[5];
    const float* Wk    = (const float*)d_in[6];
    const float* bk    = (const float*)d_in[7];
    const float* Wv    = (const float*)d_in[8];
    const float* bv    = (const float*)d_in[9];
    const float* Wo    = (const float*)d_in[10];
    const float* bo    = (const float*)d_in[11];
    float* out = (float*)d_out;

    float *pq, *pk, *pv, *pxt;
    cudaGetSymbolAddress((void**)&pq,  g_q);
    cudaGetSymbolAddress((void**)&pk,  g_k);
    cudaGetSymbolAddress((void**)&pv,  g_v);
    cudaGetSymbolAddress((void**)&pxt, g_xt);

    cudaFuncSetAttribute(flash_kernel,
                         cudaFuncAttributeMaxDynamicSharedMemorySize, FLASH_SMEM);

    dim3 gemm_grid(M_ / 64, D_ / 64);   // (128, 8)
    gemm_bias_kernel<<<gemm_grid, 256>>>(query, Wq, bq, pq, M_, D_, D_);
    gemm_bias_kernel<<<gemm_grid, 256>>>(key,   Wk, bk, pk, M_, D_, D_);
    gemm_bias_kernel<<<gemm_grid, 256>>>(value, Wv, bv, pv, M_, D_, D_);

    flash_kernel<<<dim3(L_ / 64, H_, B_), 256, FLASH_SMEM>>>(mask);

    gemm_bias_kernel<<<gemm_grid, 256>>>(pxt, Wo, bo, out, M_, D_, D_);
}

// round 2
// speedup vs baseline: 2.7988x; 2.7988x over previous
#include <cuda_runtime.h>
#include <cstdint>

// Problem constants
#define B_  4
#define L_  2048
#define D_  512
#define H_  8
#define DK_ 64
#define M_  (B_ * L_)   // 8192 rows for projection GEMMs

// Scratch: Q/K/V projections [B, L, H, DK]; attention output in the
// reference's flattening order [H, Lq, B, Dv].
__device__ float g_q[B_ * L_ * H_ * DK_];
__device__ float g_k[B_ * L_ * H_ * DK_];
__device__ float g_v[B_ * L_ * H_ * DK_];
__device__ float g_xt[B_ * L_ * H_ * DK_];

// ---------------------------------------------------------------------------
// tf32 helpers
// ---------------------------------------------------------------------------
__device__ __forceinline__ unsigned f2t(float x) {
    unsigned u;
    asm("cvt.rna.tf32.f32 %0, %1;" : "=r"(u) : "f"(x));
    return u;
}

__device__ __forceinline__ void mma_tf32(float c[4], const unsigned a[4],
                                         unsigned b0, unsigned b1) {
    asm("mma.sync.aligned.m16n8k8.row.col.f32.tf32.tf32.f32 "
        "{%0,%1,%2,%3}, {%4,%5,%6,%7}, {%8,%9}, {%0,%1,%2,%3};\n"
        : "+f"(c[0]), "+f"(c[1]), "+f"(c[2]), "+f"(c[3])
        : "r"(a[0]), "r"(a[1]), "r"(a[2]), "r"(a[3]), "r"(b0), "r"(b1));
}

// ---------------------------------------------------------------------------
// GEMM + bias (tf32 tensor cores): C[M,N] = A[M,K] @ W[K,N] + bias[N]
// CTA tile 128x128, BK=32, 256 threads = 8 warps, warp tile 64x32.
// As: [128][36] (bank = 4g+c, conflict-free), Bs: [32][136] (bank = 8c+g).
// ---------------------------------------------------------------------------
#define AP 36
#define BP 136

__global__ __launch_bounds__(256)
void gemm_bias_tc(const float* __restrict__ A, const float* __restrict__ W,
                  const float* __restrict__ bias, float* __restrict__ C,
                  int M, int N, int K)
{
    __shared__ unsigned As[128 * AP];
    __shared__ unsigned Bs[32 * BP];

    const int tid  = threadIdx.x;
    const int warp = tid >> 5;
    const int lane = tid & 31;
    const int g    = lane >> 2;     // group id 0..7
    const int c    = lane & 3;      // thread-in-group 0..3
    const int wr   = warp >> 2;     // 0..1 (64 rows each)
    const int wc   = warp & 3;      // 0..3 (32 cols each)
    const int m0   = blockIdx.x << 7;
    const int n0   = blockIdx.y << 7;

    float acc[4][4][4];             // [mt][nt][reg]
#pragma unroll
    for (int mt = 0; mt < 4; mt++)
#pragma unroll
        for (int nt = 0; nt < 4; nt++)
#pragma unroll
            for (int r = 0; r < 4; r++) acc[mt][nt][r] = 0.f;

    for (int kb = 0; kb < K; kb += 32) {
        // A tile 128x32 -> tf32
#pragma unroll
        for (int i = 0; i < 4; i++) {
            int f = tid + (i << 8);
            int row = f >> 3;
            int kq  = (f & 7) << 2;
            float4 a4 = *reinterpret_cast<const float4*>(
                A + (size_t)(m0 + row) * K + kb + kq);
            uint4 u = {f2t(a4.x), f2t(a4.y), f2t(a4.z), f2t(a4.w)};
            *reinterpret_cast<uint4*>(&As[row * AP + kq]) = u;
        }
        // B tile 32x128 -> tf32
#pragma unroll
        for (int i = 0; i < 4; i++) {
            int f = tid + (i << 8);
            int kk = f >> 5;
            int nq = (f & 31) << 2;
            float4 b4 = *reinterpret_cast<const float4*>(
                W + (size_t)(kb + kk) * N + n0 + nq);
            uint4 u = {f2t(b4.x), f2t(b4.y), f2t(b4.z), f2t(b4.w)};
            *reinterpret_cast<uint4*>(&Bs[kk * BP + nq]) = u;
        }
        __syncthreads();

#pragma unroll
        for (int ks = 0; ks < 4; ks++) {
            unsigned a[4][4], b[4][2];
#pragma unroll
            for (int mt = 0; mt < 4; mt++) {
                int row = wr * 64 + mt * 16 + g;
                int col = ks * 8 + c;
                a[mt][0] = As[row * AP + col];
                a[mt][1] = As[(row + 8) * AP + col];
                a[mt][2] = As[row * AP + col + 4];
                a[mt][3] = As[(row + 8) * AP + col + 4];
            }
#pragma unroll
            for (int nt = 0; nt < 4; nt++) {
                int col = wc * 32 + nt * 8 + g;
                b[nt][0] = Bs[(ks * 8 + c) * BP + col];
                b[nt][1] = Bs[(ks * 8 + c + 4) * BP + col];
            }
#pragma unroll
            for (int mt = 0; mt < 4; mt++)
#pragma unroll
                for (int nt = 0; nt < 4; nt++)
                    mma_tf32(acc[mt][nt], a[mt], b[nt][0], b[nt][1]);
        }
        __syncthreads();
    }

    // Epilogue: bias + store (c0,c1 row g; c2,c3 row g+8; cols 2c,2c+1)
#pragma unroll
    for (int nt = 0; nt < 4; nt++) {
        int col = n0 + wc * 32 + nt * 8 + 2 * c;
        float bx = bias[col], by = bias[col + 1];
#pragma unroll
        for (int mt = 0; mt < 4; mt++) {
            int row = m0 + wr * 64 + mt * 16 + g;
            float2 v0 = {acc[mt][nt][0] + bx, acc[mt][nt][1] + by};
            float2 v1 = {acc[mt][nt][2] + bx, acc[mt][nt][3] + by};
            *reinterpret_cast<float2*>(C + (size_t)row * N + col) = v0;
            *reinterpret_cast<float2*>(C + (size_t)(row + 8) * N + col) = v1;
        }
    }
}

// ---------------------------------------------------------------------------
// Flash attention on tensor cores (tf32 mma, fp32 softmax).
// CTA = 64 q-rows, 4 warps (one m16 tile each), loop over 64-kv tiles.
// Ks[64][68], Vs[64][72] (conflict-free frag reads), Ps per-warp [16][68].
// ---------------------------------------------------------------------------
#define KP 68
#define VP 72
#define PP 68
#define FLASH_SMEM ((64 * KP + 64 * VP + 4 * 16 * PP) * 4)

__global__ __launch_bounds__(128)
void flash_tc(const float* __restrict__ mask)
{
    extern __shared__ unsigned smu[];
    unsigned* Ks = smu;                       // [kv][d]   pitch KP
    unsigned* Vs = Ks + 64 * KP;              // [kv][dv]  pitch VP
    unsigned* Ps = Vs + 64 * VP;              // per-warp [16][PP]

    const int tid  = threadIdx.x;
    const int warp = tid >> 5;
    const int lane = tid & 31;
    const int g    = lane >> 2;
    const int c    = lane & 3;
    const int q0   = blockIdx.x << 6;
    const int h    = blockIdx.y;
    const int b    = blockIdx.z;
    const float scale = 0.125f;

    unsigned* Pw = Ps + warp * 16 * PP;
    const int qrow = q0 + warp * 16;          // warp's first q row

    // Q fragments in registers: q[ks][4] covers d = ks*8..ks*8+7
    unsigned qf[8][4];
    {
        const float* qp = g_q + (((size_t)b * L_ + qrow) * H_ + h) * DK_;
#pragma unroll
        for (int ks = 0; ks < 8; ks++) {
            int d0 = ks * 8 + c;
            qf[ks][0] = f2t(qp[(size_t)(g)     * (H_ * DK_) + d0]);
            qf[ks][1] = f2t(qp[(size_t)(g + 8) * (H_ * DK_) + d0]);
            qf[ks][2] = f2t(qp[(size_t)(g)     * (H_ * DK_) + d0 + 4]);
            qf[ks][3] = f2t(qp[(size_t)(g + 8) * (H_ * DK_) + d0 + 4]);
        }
    }

    float o[8][4];
    float m0 = -1e30f, m1 = -1e30f, l0 = 0.f, l1 = 0.f;
#pragma unroll
    for (int nt = 0; nt < 8; nt++)
#pragma unroll
        for (int r = 0; r < 4; r++) o[nt][r] = 0.f;

    for (int k0 = 0; k0 < L_; k0 += 64) {
        __syncthreads();   // previous iteration's Ks/Vs reads complete

        // Fill K/V tiles (64 x 64 each), tf32-converted
#pragma unroll
        for (int i = 0; i < 8; i++) {
            int f   = tid + (i << 7);
            int row = f >> 4;
            int dq  = (f & 15) << 2;
            size_t base = (((size_t)b * L_ + k0 + row) * H_ + h) * DK_ + dq;
            float4 kv4 = *reinterpret_cast<const float4*>(g_k + base);
            uint4 ku = {f2t(kv4.x), f2t(kv4.y), f2t(kv4.z), f2t(kv4.w)};
            *reinterpret_cast<uint4*>(&Ks[row * KP + dq]) = ku;
            float4 vv4 = *reinterpret_cast<const float4*>(g_v + base);
            uint4 vu = {f2t(vv4.x), f2t(vv4.y), f2t(vv4.z), f2t(vv4.w)};
            *reinterpret_cast<uint4*>(&Vs[row * VP + dq]) = vu;
        }
        __syncthreads();

        // S = Q K^T  (m16 x n64 x k64)
        float s[8][4];
#pragma unroll
        for (int nt = 0; nt < 8; nt++)
#pragma unroll
            for (int r = 0; r < 4; r++) s[nt][r] = 0.f;

#pragma unroll
        for (int ks = 0; ks < 8; ks++) {
            int d0 = ks * 8 + c;
#pragma unroll
            for (int nt = 0; nt < 8; nt++) {
                int kvr = nt * 8 + g;
                unsigned b0 = Ks[kvr * KP + d0];
                unsigned b1 = Ks[kvr * KP + d0 + 4];
                mma_tf32(s[nt], qf[ks], b0, b1);
            }
        }

        // scale + mask
        {
            const float* mrow0 = mask + (size_t)(q0 + warp * 16 + g) * L_ + k0;
            const float* mrow1 = mrow0 + 8 * L_;
#pragma unroll
            for (int nt = 0; nt < 8; nt++) {
                int col = nt * 8 + 2 * c;
                float2 mv0 = *reinterpret_cast<const float2*>(mrow0 + col);
                float2 mv1 = *reinterpret_cast<const float2*>(mrow1 + col);
                s[nt][0] = fmaf(s[nt][0], scale, mv0.x);
                s[nt][1] = fmaf(s[nt][1], scale, mv0.y);
                s[nt][2] = fmaf(s[nt][2], scale, mv1.x);
                s[nt][3] = fmaf(s[nt][3], scale, mv1.y);
            }
        }

        // online softmax (rows g and g+8 of warp tile)
        float mx0 = -1e30f, mx1 = -1e30f;
#pragma unroll
        for (int nt = 0; nt < 8; nt++) {
            mx0 = fmaxf(mx0, fmaxf(s[nt][0], s[nt][1]));
            mx1 = fmaxf(mx1, fmaxf(s[nt][2], s[nt][3]));
        }
        mx0 = fmaxf(mx0, __shfl_xor_sync(0xffffffffu, mx0, 1));
        mx0 = fmaxf(mx0, __shfl_xor_sync(0xffffffffu, mx0, 2));
        mx1 = fmaxf(mx1, __shfl_xor_sync(0xffffffffu, mx1, 1));
        mx1 = fmaxf(mx1, __shfl_xor_sync(0xffffffffu, mx1, 2));

        float mn0 = fmaxf(m0, mx0), mn1 = fmaxf(m1, mx1);
        float a0 = __expf(m0 - mn0), a1 = __expf(m1 - mn1);
        m0 = mn0; m1 = mn1;

        float rs0 = 0.f, rs1 = 0.f;
#pragma unroll
        for (int nt = 0; nt < 8; nt++) {
            float p0 = __expf(s[nt][0] - mn0);
            float p1 = __expf(s[nt][1] - mn0);
            float p2 = __expf(s[nt][2] - mn1);
            float p3 = __expf(s[nt][3] - mn1);
            rs0 += p0 + p1;  rs1 += p2 + p3;
            int col = nt * 8 + 2 * c;
            Pw[g * PP + col]           = f2t(p0);
            Pw[g * PP + col + 1]       = f2t(p1);
            Pw[(g + 8) * PP + col]     = f2t(p2);
            Pw[(g + 8) * PP + col + 1] = f2t(p3);
        }
        rs0 += __shfl_xor_sync(0xffffffffu, rs0, 1);
        rs0 += __shfl_xor_sync(0xffffffffu, rs0, 2);
        rs1 += __shfl_xor_sync(0xffffffffu, rs1, 1);
        rs1 += __shfl_xor_sync(0xffffffffu, rs1, 2);
        l0 = l0 * a0 + rs0;
        l1 = l1 * a1 + rs1;

#pragma unroll
        for (int nt = 0; nt < 8; nt++) {
            o[nt][0] *= a0; o[nt][1] *= a0;
            o[nt][2] *= a1; o[nt][3] *= a1;
        }
        __syncwarp();

        // O += P V  (m16 x n64 x k64), P read back as A fragments
#pragma unroll
        for (int ks = 0; ks < 8; ks++) {
            unsigned a[4];
            int col = ks * 8 + c;
            a[0] = Pw[g * PP + col];
            a[1] = Pw[(g + 8) * PP + col];
            a[2] = Pw[g * PP + col + 4];
            a[3] = Pw[(g + 8) * PP + col + 4];
#pragma unroll
            for (int nt = 0; nt < 8; nt++) {
                int kvr = ks * 8 + c;
                unsigned b0 = Vs[kvr * VP + nt * 8 + g];
                unsigned b1 = Vs[(kvr + 4) * VP + nt * 8 + g];
                mma_tf32(o[nt], a, b0, b1);
            }
        }
        __syncwarp();
    }

    // Epilogue: normalize, write g_xt in [H, Lq, B, Dv] flat order
    float inv0 = 1.0f / l0, inv1 = 1.0f / l1;
#pragma unroll
    for (int nt = 0; nt < 8; nt++) {
        int dv = nt * 8 + 2 * c;
        float2 v0 = {o[nt][0] * inv0, o[nt][1] * inv0};
        float2 v1 = {o[nt][2] * inv1, o[nt][3] * inv1};
        size_t base0 = (((size_t)h * L_ + qrow + g) * B_ + b) * DK_ + dv;
        size_t base1 = (((size_t)h * L_ + qrow + g + 8) * B_ + b) * DK_ + dv;
        *reinterpret_cast<float2*>(g_xt + base0) = v0;
        *reinterpret_cast<float2*>(g_xt + base1) = v1;
    }
}

// ---------------------------------------------------------------------------
extern "C" void kernel_launch(void* const* d_in, const int* in_sizes, int n_in,
                              void* d_out, int out_size)
{
    const float* query = (const float*)d_in[0];
    const float* key   = (const float*)d_in[1];
    const float* value = (const float*)d_in[2];
    const float* mask  = (const float*)d_in[3];
    const float* Wq    = (const float*)d_in[4];
    const float* bq    = (const float*)d_in[5];
    const float* Wk    = (const float*)d_in[6];
    const float* bk    = (const float*)d_in[7];
    const float* Wv    = (const float*)d_in[8];
    const float* bv    = (const float*)d_in[9];
    const float* Wo    = (const float*)d_in[10];
    const float* bo    = (const float*)d_in[11];
    float* out = (float*)d_out;

    float *pq, *pk, *pv, *pxt;
    cudaGetSymbolAddress((void**)&pq,  g_q);
    cudaGetSymbolAddress((void**)&pk,  g_k);
    cudaGetSymbolAddress((void**)&pv,  g_v);
    cudaGetSymbolAddress((void**)&pxt, g_xt);

    cudaFuncSetAttribute(flash_tc,
                         cudaFuncAttributeMaxDynamicSharedMemorySize, FLASH_SMEM);

    dim3 gemm_grid(M_ / 128, D_ / 128);   // (64, 4)
    gemm_bias_tc<<<gemm_grid, 256>>>(query, Wq, bq, pq, M_, D_, D_);
    gemm_bias_tc<<<gemm_grid, 256>>>(key,   Wk, bk, pk, M_, D_, D_);
    gemm_bias_tc<<<gemm_grid, 256>>>(value, Wv, bv, pv, M_, D_, D_);

    flash_tc<<<dim3(L_ / 64, H_, B_), 128, FLASH_SMEM>>>(mask);

    gemm_bias_tc<<<gemm_grid, 256>>>(pxt, Wo, bo, out, M_, D_, D_);
}